// round 14
// baseline (speedup 1.0000x reference)
#include <cuda_runtime.h>
#include <cstdint>

#define NN 50000
#define EE 800000
#define FIN 128
#define HH 4
#define CC 73
#define HCV 292
#define BN_EPS 1e-5f

// ---------------- scratch (static device globals) ----------------
__device__ __align__(16) float g_xl[(size_t)NN * HCV];
__device__ __align__(16) float g_xr[(size_t)NN * HCV];
__device__ __align__(16) float g_h [(size_t)NN * HCV];
__device__ float g_stats[2][2 * HCV];          // per-layer sum / sumsq buffers
__device__ __align__(16) float g_bnsc[HCV];
__device__ __align__(16) float g_bnbt[HCV];
__device__ int   g_src[EE];
__device__ int   g_cnt[NN];
__device__ int   g_off[NN];
__device__ int   g_fill[NN];
__device__ int   g_csrc[EE];
__device__ int   g_is64;

#define SCAN_BLKS 196                       // ceil(50000/256)
__device__ int   g_bsum[SCAN_BLKS];
__device__ int   g_boff[SCAN_BLKS];

// ---------------- zero counters + stats + edge dtype detect (merged) ----------------
__global__ void zero_cnt_detect(const unsigned int* ei) {
    int i = blockIdx.x * blockDim.x + threadIdx.x;
    if (i < NN) { g_cnt[i] = 0; g_fill[i] = 0; }
    if (i < 4 * HCV) ((float*)g_stats)[i] = 0.f;
    if (blockIdx.x == 0 && threadIdx.x < 32) {
        unsigned acc = 0;
        for (int k = threadIdx.x; k < 2048; k += 32) acc |= ei[2 * k + 1];
        #pragma unroll
        for (int o = 16; o; o >>= 1) acc |= __shfl_xor_sync(0xffffffffu, acc, o);
        if (threadIdx.x == 0) g_is64 = (acc == 0u) ? 1 : 0;
    }
}

__global__ void convert_hist(const void* ei) {
    int i = blockIdx.x * blockDim.x + threadIdx.x;
    if (i >= EE) return;
    int s, d;
    if (g_is64) {
        const long long* p = (const long long*)ei;
        s = (int)p[i]; d = (int)p[EE + i];
    } else {
        const int* p = (const int*)ei;
        s = p[i]; d = p[EE + i];
    }
    g_src[i] = s;
    atomicAdd(&g_cnt[d], 1);
}

// ---------------- hierarchical exclusive scan of g_cnt -> g_off ----------------
__global__ void scan_blocksum() {
    __shared__ int sh[256];
    int i = blockIdx.x * 256 + threadIdx.x;
    int v = (i < NN) ? g_cnt[i] : 0;
    sh[threadIdx.x] = v;
    __syncthreads();
    for (int o = 128; o; o >>= 1) {
        if (threadIdx.x < o) sh[threadIdx.x] += sh[threadIdx.x + o];
        __syncthreads();
    }
    if (threadIdx.x == 0) g_bsum[blockIdx.x] = sh[0];
}
__global__ void scan_top() {
    __shared__ int sh[256];
    int t = threadIdx.x;
    sh[t] = (t < SCAN_BLKS) ? g_bsum[t] : 0;
    __syncthreads();
    for (int o = 1; o < 256; o <<= 1) {
        int v = (t >= o) ? sh[t - o] : 0;
        __syncthreads();
        sh[t] += v;
        __syncthreads();
    }
    if (t < SCAN_BLKS) g_boff[t] = (t == 0) ? 0 : sh[t - 1];
}
__global__ void scan_local() {
    __shared__ int sh[256];
    int t = threadIdx.x;
    int i = blockIdx.x * 256 + t;
    int v = (i < NN) ? g_cnt[i] : 0;
    sh[t] = v;
    __syncthreads();
    for (int o = 1; o < 256; o <<= 1) {
        int u = (t >= o) ? sh[t - o] : 0;
        __syncthreads();
        sh[t] += u;
        __syncthreads();
    }
    if (i < NN) g_off[i] = g_boff[blockIdx.x] + sh[t] - v;   // exclusive
}

__global__ void scatter_csr(const void* ei) {
    int e = blockIdx.x * blockDim.x + threadIdx.x;
    if (e >= EE) return;
    int d;
    if (g_is64) d = (int)((const long long*)ei)[EE + e];
    else        d = ((const int*)ei)[EE + e];
    int p = g_off[d] + atomicAdd(&g_fill[d], 1);
    g_csrc[p] = g_src[e];
}

// ---------------- TF32 tensor-core stacked GEMM (double-buffered smem) ----------------
#define PAD 36
#define GEMM_BM 128
#define GEMM_BN 64
#define GEMM_BK 32
#define SMEM_WORDS_A (GEMM_BM * PAD)
#define SMEM_WORDS_B (GEMM_BN * PAD)
#define GEMM_SMEM_BYTES ((2 * SMEM_WORDS_A + 2 * SMEM_WORDS_B) * 4)

__device__ __forceinline__ uint32_t f2tf32(float f) {
    uint32_t r;
    asm("cvt.rna.tf32.f32 %0, %1;" : "=r"(r) : "f"(f));
    return r;
}

__global__ __launch_bounds__(256, 2)
void gemm2_tc(const float* __restrict__ A,
              const float* __restrict__ Wl, const float* __restrict__ Wr,
              const float* __restrict__ bl, const float* __restrict__ br,
              float* __restrict__ Cl, float* __restrict__ Cr,
              int nrows, int K) {
    const int BM = GEMM_BM, BN = GEMM_BN, BK = GEMM_BK, NTOT = 2 * HCV;
    extern __shared__ uint32_t smem_dyn[];
    uint32_t* AsBase = smem_dyn;
    uint32_t* BsBase = smem_dyn + 2 * SMEM_WORDS_A;

    int tid  = threadIdx.x;
    int wid  = tid >> 5, lane = tid & 31;
    int wm   = wid & 3, wn = wid >> 2;
    int g    = lane >> 2, tig = lane & 3;
    int row0 = blockIdx.x * BM, col0 = blockIdx.y * BN;

    int arow = tid >> 1;
    int brow = tid >> 2;

    float acc[2][4][4];
    #pragma unroll
    for (int m = 0; m < 2; m++)
        #pragma unroll
        for (int n = 0; n < 4; n++)
            #pragma unroll
            for (int c = 0; c < 4; c++) acc[m][n][c] = 0.f;

    int nChunks = (K + BK - 1) / BK;
    float4 pa[4], pb[2];

    auto fetch = [&](int k0) {
        const float* Arow = A + (size_t)(row0 + arow) * K;
        bool rok = (row0 + arow) < nrows;
        #pragma unroll
        for (int j = 0; j < 4; j++) {
            int c = (tid & 1) * 16 + j * 4;
            bool ok = rok && (k0 + c + 4 <= K);
            pa[j] = ok ? *reinterpret_cast<const float4*>(Arow + k0 + c)
                       : make_float4(0.f, 0.f, 0.f, 0.f);
        }
        int gn = col0 + brow;
        const float* Wrow = (gn < HCV) ? (Wl + (size_t)gn * K)
                         : (gn < NTOT) ? (Wr + (size_t)(gn - HCV) * K) : nullptr;
        #pragma unroll
        for (int j = 0; j < 2; j++) {
            int c = (tid & 3) * 8 + j * 4;
            bool ok = Wrow && (k0 + c + 4 <= K);
            pb[j] = ok ? *reinterpret_cast<const float4*>(Wrow + k0 + c)
                       : make_float4(0.f, 0.f, 0.f, 0.f);
        }
    };

    auto store_buf = [&](int buf) {
        uint32_t* As = AsBase + buf * SMEM_WORDS_A;
        uint32_t* Bs = BsBase + buf * SMEM_WORDS_B;
        #pragma unroll
        for (int j = 0; j < 4; j++) {
            int c = (tid & 1) * 16 + j * 4;
            uint32_t* d = &As[arow * PAD + c];
            d[0] = f2tf32(pa[j].x); d[1] = f2tf32(pa[j].y);
            d[2] = f2tf32(pa[j].z); d[3] = f2tf32(pa[j].w);
        }
        #pragma unroll
        for (int j = 0; j < 2; j++) {
            int c = (tid & 3) * 8 + j * 4;
            uint32_t* d = &Bs[brow * PAD + c];
            d[0] = f2tf32(pb[j].x); d[1] = f2tf32(pb[j].y);
            d[2] = f2tf32(pb[j].z); d[3] = f2tf32(pb[j].w);
        }
    };

    fetch(0);
    store_buf(0);
    __syncthreads();

    for (int ch = 0; ch < nChunks; ch++) {
        if (ch + 1 < nChunks) fetch((ch + 1) * BK);

        const uint32_t* As = AsBase + (ch & 1) * SMEM_WORDS_A;
        const uint32_t* Bs = BsBase + (ch & 1) * SMEM_WORDS_B;
        #pragma unroll
        for (int kk = 0; kk < 4; kk++) {
            int kb = kk * 8;
            uint32_t af[2][4], bf[4][2];
            #pragma unroll
            for (int m = 0; m < 2; m++) {
                int r = wm * 32 + m * 16 + g;
                af[m][0] = As[r * PAD + kb + tig];
                af[m][1] = As[(r + 8) * PAD + kb + tig];
                af[m][2] = As[r * PAD + kb + tig + 4];
                af[m][3] = As[(r + 8) * PAD + kb + tig + 4];
            }
            #pragma unroll
            for (int n = 0; n < 4; n++) {
                int r = wn * 32 + n * 8 + g;
                bf[n][0] = Bs[r * PAD + kb + tig];
                bf[n][1] = Bs[r * PAD + kb + tig + 4];
            }
            #pragma unroll
            for (int m = 0; m < 2; m++)
                #pragma unroll
                for (int n = 0; n < 4; n++) {
                    asm volatile(
                        "mma.sync.aligned.m16n8k8.row.col.f32.tf32.tf32.f32 "
                        "{%0,%1,%2,%3}, {%4,%5,%6,%7}, {%8,%9}, {%0,%1,%2,%3};\n"
                        : "+f"(acc[m][n][0]), "+f"(acc[m][n][1]),
                          "+f"(acc[m][n][2]), "+f"(acc[m][n][3])
                        : "r"(af[m][0]), "r"(af[m][1]), "r"(af[m][2]), "r"(af[m][3]),
                          "r"(bf[n][0]), "r"(bf[n][1]));
                }
        }

        if (ch + 1 < nChunks) {
            store_buf((ch + 1) & 1);
            __syncthreads();
        }
    }

    // -------- epilogue --------
    #pragma unroll
    for (int m = 0; m < 2; m++) {
        int gr0 = row0 + wm * 32 + m * 16 + g;
        int gr1 = gr0 + 8;
        #pragma unroll
        for (int n = 0; n < 4; n++) {
            int gc = col0 + wn * 32 + n * 8 + 2 * tig;
            float bia0, bia1;
            float *base;
            int cc;
            if (gc < HCV) {
                bia0 = __ldg(&bl[gc]); bia1 = __ldg(&bl[gc + 1]);
                base = Cl; cc = gc;
            } else if (gc < NTOT) {
                cc = gc - HCV;
                bia0 = __ldg(&br[cc]); bia1 = __ldg(&br[cc + 1]);
                base = Cr;
            } else continue;
            if (gr0 < nrows) {
                base[(size_t)gr0 * HCV + cc]     = acc[m][n][0] + bia0;
                base[(size_t)gr0 * HCV + cc + 1] = acc[m][n][1] + bia1;
            }
            if (gr1 < nrows) {
                base[(size_t)gr1 * HCV + cc]     = acc[m][n][2] + bia0;
                base[(size_t)gr1 * HCV + cc + 1] = acc[m][n][3] + bia1;
            }
        }
    }
}

// ---------------- GATv2 node kernel: warp per (node, head-pair), half-warp per head ----
// lanes 0-15 -> head 2p, lanes 16-31 -> head 2p+1. The two heads are contiguous in
// memory (584 B slice per warp gather). Scores bounded -> plain exp (max cancels).
__global__ __launch_bounds__(128, 12)
void gat_node(const float* __restrict__ att, const float* __restrict__ b) {
    int wg   = blockIdx.x * 4 + (threadIdx.x >> 5);   // global warp id
    int n    = wg >> 1;                               // node
    int pair = wg & 1;                                // head pair: {0,1} or {2,3}
    if (n >= NN) return;
    int lane = threadIdx.x & 31;
    int hl   = lane & 15;                             // lane within half-warp
    int head = pair * 2 + (lane >> 4);

    size_t base = (size_t)n * HCV + head * CC;
    const float* atth = att + head * CC;

    float xrr[5], attv[5], out[5];
    #pragma unroll
    for (int j = 0; j < 5; j++) {
        int c = hl + 16 * j;
        bool ok = c < CC;
        xrr[j]  = ok ? g_xr[base + c] : 0.f;
        attv[j] = ok ? __ldg(&atth[c]) : 0.f;
        out[j]  = 0.f;
    }
    int beg = g_off[n], cnt = g_cnt[n];

    float den = 0.f;
    for (int i = 0; i < cnt; i++) {
        const float* xl = g_xl + (size_t)__ldg(&g_csrc[beg + i]) * HCV + head * CC;
        float xv[5];
        float s = 0.f;
        #pragma unroll
        for (int j = 0; j < 5; j++) {
            int c = hl + 16 * j;
            float v = (c < CC) ? xl[c] : 0.f;
            xv[j] = v;
            float f = v + xrr[j];
            f = (f >= 0.f) ? f : 0.2f * f;
            s += f * attv[j];
        }
        #pragma unroll
        for (int o = 1; o < 16; o <<= 1) s += __shfl_xor_sync(0xffffffffu, s, o);

        float e = __expf(s);
        den += e;
        #pragma unroll
        for (int j = 0; j < 5; j++) out[j] += e * xv[j];
    }
    float inv = 1.f / (den + 1e-16f);
    #pragma unroll
    for (int j = 0; j < 5; j++) {
        int c = hl + 16 * j;
        if (c < CC)
            g_h[base + c] = out[j] * inv + __ldg(&b[head * CC + c]);
    }
}

// ---------------- batchnorm ----------------
__global__ void bn_stats(int layer) {
    int t = threadIdx.x;
    if (t >= HCV) return;
    float s = 0.f, sq = 0.f;
    for (int n = blockIdx.x; n < NN; n += gridDim.x) {
        float v = g_h[(size_t)n * HCV + t];
        s += v; sq += v * v;
    }
    atomicAdd(&g_stats[layer][t], s);
    atomicAdd(&g_stats[layer][HCV + t], sq);
}
__global__ void bn_prep(int layer, const float* __restrict__ gamma,
                        const float* __restrict__ beta) {
    int t = threadIdx.x;
    if (t >= HCV) return;
    float mu = g_stats[layer][t] * (1.f / NN);
    float var = g_stats[layer][HCV + t] * (1.f / NN) - mu * mu;
    float sc = rsqrtf(var + BN_EPS) * gamma[t];
    g_bnsc[t] = sc;
    g_bnbt[t] = beta[t] - mu * sc;
}
// flat float4 BN+leaky over g_h: row stride 292 floats = 73 float4
__global__ void bn_apply_v4() {
    int idx = blockIdx.x * blockDim.x + threadIdx.x;
    if (idx >= NN * 73) return;
    int c4 = idx % 73;
    float4 v  = reinterpret_cast<float4*>(g_h)[idx];
    float4 sc = reinterpret_cast<const float4*>(g_bnsc)[c4];
    float4 bt = reinterpret_cast<const float4*>(g_bnbt)[c4];
    float y;
    y = v.x * sc.x + bt.x; v.x = (y >= 0.f) ? y : 0.01f * y;
    y = v.y * sc.y + bt.y; v.y = (y >= 0.f) ? y : 0.01f * y;
    y = v.z * sc.z + bt.z; v.z = (y >= 0.f) ? y : 0.01f * y;
    y = v.w * sc.w + bt.w; v.w = (y >= 0.f) ? y : 0.01f * y;
    reinterpret_cast<float4*>(g_h)[idx] = v;
}

// ---------------- fused layer-2 BN + leaky + classifier ----------------
__global__ void bn_classify(const float* __restrict__ Wc, const float* __restrict__ bc,
                            float* __restrict__ out) {
    int w = (blockIdx.x * blockDim.x + threadIdx.x) >> 5;
    int lane = threadIdx.x & 31;
    if (w >= NN) return;
    const float* hrow = g_h + (size_t)w * HCV;
    float c0 = 0.f, c1 = 0.f;
    #pragma unroll
    for (int k = 0; k < 10; k++) {
        int j = lane + 32 * k;
        if (j < HCV) {
            float y = hrow[j] * __ldg(&g_bnsc[j]) + __ldg(&g_bnbt[j]);
            y = (y >= 0.f) ? y : 0.01f * y;
            c0 += y * __ldg(&Wc[j]);
            c1 += y * __ldg(&Wc[HCV + j]);
        }
    }
    #pragma unroll
    for (int o = 16; o; o >>= 1) {
        c0 += __shfl_xor_sync(0xffffffffu, c0, o);
        c1 += __shfl_xor_sync(0xffffffffu, c1, o);
    }
    if (lane == 0) {
        out[2 * w]     = c0 + bc[0];
        out[2 * w + 1] = c1 + bc[1];
    }
}

// ---------------- host orchestration ----------------
extern "C" void kernel_launch(void* const* d_in, const int* in_sizes, int n_in,
                              void* d_out, int out_size) {
    const float* x    = (const float*)d_in[0];
    const void*  ei   = d_in[1];
    const float* Wl1  = (const float*)d_in[2];
    const float* bl1  = (const float*)d_in[3];
    const float* Wr1  = (const float*)d_in[4];
    const float* br1  = (const float*)d_in[5];
    const float* att1 = (const float*)d_in[6];
    const float* b1   = (const float*)d_in[7];
    const float* Wl2  = (const float*)d_in[8];
    const float* bl2  = (const float*)d_in[9];
    const float* Wr2  = (const float*)d_in[10];
    const float* br2  = (const float*)d_in[11];
    const float* att2 = (const float*)d_in[12];
    const float* b2   = (const float*)d_in[13];
    const float* gamma = (const float*)d_in[14];
    const float* beta  = (const float*)d_in[15];
    const float* Wc   = (const float*)d_in[16];
    const float* bc   = (const float*)d_in[17];
    float* out = (float*)d_out;

    float *xl, *xr, *h;
    cudaGetSymbolAddress((void**)&xl, g_xl);
    cudaGetSymbolAddress((void**)&xr, g_xr);
    cudaGetSymbolAddress((void**)&h,  g_h);

    static int smem_set = 0;
    if (!smem_set) {
        cudaFuncSetAttribute(gemm2_tc, cudaFuncAttributeMaxDynamicSharedMemorySize,
                             GEMM_SMEM_BYTES);
        smem_set = 1;
    }

    zero_cnt_detect<<<(NN + 255) / 256, 256>>>((const unsigned int*)ei);
    convert_hist<<<(EE + 255) / 256, 256>>>(ei);
    scan_blocksum<<<SCAN_BLKS, 256>>>();
    scan_top<<<1, 256>>>();
    scan_local<<<SCAN_BLKS, 256>>>();
    scatter_csr<<<(EE + 255) / 256, 256>>>(ei);

    dim3 ggrid((NN + 127) / 128, (2 * HCV + 63) / 64);     // (391, 10)
    const int gatBlocks = (NN * 2 + 3) / 4;                // 25000

    // ---- layer 1 ----
    gemm2_tc<<<ggrid, 256, GEMM_SMEM_BYTES>>>(x, Wl1, Wr1, bl1, br1, xl, xr, NN, FIN);
    gat_node<<<gatBlocks, 128>>>(att1, b1);
    bn_stats<<<512, 320>>>(0);
    bn_prep<<<1, 320>>>(0, gamma, beta);
    bn_apply_v4<<<(NN * 73 + 255) / 256, 256>>>();

    // ---- layer 2 ----
    gemm2_tc<<<ggrid, 256, GEMM_SMEM_BYTES>>>(h, Wl2, Wr2, bl2, br2, xl, xr, NN, HCV);
    gat_node<<<gatBlocks, 128>>>(att2, b2);
    bn_stats<<<512, 320>>>(1);
    bn_prep<<<1, 320>>>(1, gamma, beta);
    bn_classify<<<(NN * 32 + 255) / 256, 256>>>(Wc, bc, out);
}

// round 15
// speedup vs baseline: 1.3724x; 1.3724x over previous
#include <cuda_runtime.h>
#include <cstdint>

#define NN 50000
#define EE 800000
#define FIN 128
#define HH 4
#define CC 73
#define HCV 292
#define BN_EPS 1e-5f

// ---------------- scratch (static device globals) ----------------
__device__ __align__(16) float g_xl[(size_t)NN * HCV];
__device__ __align__(16) float g_xr[(size_t)NN * HCV];
__device__ __align__(16) float g_h [(size_t)NN * HCV];
__device__ float g_stats[2][2 * HCV];          // per-layer sum / sumsq buffers
__device__ __align__(16) float g_bnsc[HCV];
__device__ __align__(16) float g_bnbt[HCV];
__device__ int   g_src[EE];
__device__ int   g_cnt[NN];
__device__ int   g_off[NN];
__device__ int   g_fill[NN];
__device__ int   g_csrc[EE];
__device__ int   g_is64;

#define SCAN_BLKS 196                       // ceil(50000/256)
__device__ int   g_bsum[SCAN_BLKS];
__device__ int   g_boff[SCAN_BLKS];

// ---------------- zero counters + stats + edge dtype detect (merged) ----------------
__global__ void zero_cnt_detect(const unsigned int* ei) {
    int i = blockIdx.x * blockDim.x + threadIdx.x;
    if (i < NN) { g_cnt[i] = 0; g_fill[i] = 0; }
    if (i < 4 * HCV) ((float*)g_stats)[i] = 0.f;
    if (blockIdx.x == 0 && threadIdx.x < 32) {
        unsigned acc = 0;
        for (int k = threadIdx.x; k < 2048; k += 32) acc |= ei[2 * k + 1];
        #pragma unroll
        for (int o = 16; o; o >>= 1) acc |= __shfl_xor_sync(0xffffffffu, acc, o);
        if (threadIdx.x == 0) g_is64 = (acc == 0u) ? 1 : 0;
    }
}

__global__ void convert_hist(const void* ei) {
    int i = blockIdx.x * blockDim.x + threadIdx.x;
    if (i >= EE) return;
    int s, d;
    if (g_is64) {
        const long long* p = (const long long*)ei;
        s = (int)p[i]; d = (int)p[EE + i];
    } else {
        const int* p = (const int*)ei;
        s = p[i]; d = p[EE + i];
    }
    g_src[i] = s;
    atomicAdd(&g_cnt[d], 1);
}

// ---------------- hierarchical exclusive scan of g_cnt -> g_off ----------------
__global__ void scan_blocksum() {
    __shared__ int sh[256];
    int i = blockIdx.x * 256 + threadIdx.x;
    int v = (i < NN) ? g_cnt[i] : 0;
    sh[threadIdx.x] = v;
    __syncthreads();
    for (int o = 128; o; o >>= 1) {
        if (threadIdx.x < o) sh[threadIdx.x] += sh[threadIdx.x + o];
        __syncthreads();
    }
    if (threadIdx.x == 0) g_bsum[blockIdx.x] = sh[0];
}
__global__ void scan_top() {
    __shared__ int sh[256];
    int t = threadIdx.x;
    sh[t] = (t < SCAN_BLKS) ? g_bsum[t] : 0;
    __syncthreads();
    for (int o = 1; o < 256; o <<= 1) {
        int v = (t >= o) ? sh[t - o] : 0;
        __syncthreads();
        sh[t] += v;
        __syncthreads();
    }
    if (t < SCAN_BLKS) g_boff[t] = (t == 0) ? 0 : sh[t - 1];
}
__global__ void scan_local() {
    __shared__ int sh[256];
    int t = threadIdx.x;
    int i = blockIdx.x * 256 + t;
    int v = (i < NN) ? g_cnt[i] : 0;
    sh[t] = v;
    __syncthreads();
    for (int o = 1; o < 256; o <<= 1) {
        int u = (t >= o) ? sh[t - o] : 0;
        __syncthreads();
        sh[t] += u;
        __syncthreads();
    }
    if (i < NN) g_off[i] = g_boff[blockIdx.x] + sh[t] - v;   // exclusive
}

__global__ void scatter_csr(const void* ei) {
    int e = blockIdx.x * blockDim.x + threadIdx.x;
    if (e >= EE) return;
    int d;
    if (g_is64) d = (int)((const long long*)ei)[EE + e];
    else        d = ((const int*)ei)[EE + e];
    int p = g_off[d] + atomicAdd(&g_fill[d], 1);
    g_csrc[p] = g_src[e];
}

// ---------------- TF32 tensor-core stacked GEMM (double-buffered smem) ----------------
#define PAD 36
#define GEMM_BM 128
#define GEMM_BN 64
#define GEMM_BK 32
#define SMEM_WORDS_A (GEMM_BM * PAD)
#define SMEM_WORDS_B (GEMM_BN * PAD)
#define GEMM_SMEM_BYTES ((2 * SMEM_WORDS_A + 2 * SMEM_WORDS_B) * 4)

__device__ __forceinline__ uint32_t f2tf32(float f) {
    uint32_t r;
    asm("cvt.rna.tf32.f32 %0, %1;" : "=r"(r) : "f"(f));
    return r;
}

__global__ __launch_bounds__(256, 2)
void gemm2_tc(const float* __restrict__ A,
              const float* __restrict__ Wl, const float* __restrict__ Wr,
              const float* __restrict__ bl, const float* __restrict__ br,
              float* __restrict__ Cl, float* __restrict__ Cr,
              int nrows, int K) {
    const int BM = GEMM_BM, BN = GEMM_BN, BK = GEMM_BK, NTOT = 2 * HCV;
    extern __shared__ uint32_t smem_dyn[];
    uint32_t* AsBase = smem_dyn;
    uint32_t* BsBase = smem_dyn + 2 * SMEM_WORDS_A;

    int tid  = threadIdx.x;
    int wid  = tid >> 5, lane = tid & 31;
    int wm   = wid & 3, wn = wid >> 2;
    int g    = lane >> 2, tig = lane & 3;
    int row0 = blockIdx.x * BM, col0 = blockIdx.y * BN;

    int arow = tid >> 1;
    int brow = tid >> 2;

    float acc[2][4][4];
    #pragma unroll
    for (int m = 0; m < 2; m++)
        #pragma unroll
        for (int n = 0; n < 4; n++)
            #pragma unroll
            for (int c = 0; c < 4; c++) acc[m][n][c] = 0.f;

    int nChunks = (K + BK - 1) / BK;
    float4 pa[4], pb[2];

    auto fetch = [&](int k0) {
        const float* Arow = A + (size_t)(row0 + arow) * K;
        bool rok = (row0 + arow) < nrows;
        #pragma unroll
        for (int j = 0; j < 4; j++) {
            int c = (tid & 1) * 16 + j * 4;
            bool ok = rok && (k0 + c + 4 <= K);
            pa[j] = ok ? *reinterpret_cast<const float4*>(Arow + k0 + c)
                       : make_float4(0.f, 0.f, 0.f, 0.f);
        }
        int gn = col0 + brow;
        const float* Wrow = (gn < HCV) ? (Wl + (size_t)gn * K)
                         : (gn < NTOT) ? (Wr + (size_t)(gn - HCV) * K) : nullptr;
        #pragma unroll
        for (int j = 0; j < 2; j++) {
            int c = (tid & 3) * 8 + j * 4;
            bool ok = Wrow && (k0 + c + 4 <= K);
            pb[j] = ok ? *reinterpret_cast<const float4*>(Wrow + k0 + c)
                       : make_float4(0.f, 0.f, 0.f, 0.f);
        }
    };

    auto store_buf = [&](int buf) {
        uint32_t* As = AsBase + buf * SMEM_WORDS_A;
        uint32_t* Bs = BsBase + buf * SMEM_WORDS_B;
        #pragma unroll
        for (int j = 0; j < 4; j++) {
            int c = (tid & 1) * 16 + j * 4;
            uint32_t* d = &As[arow * PAD + c];
            d[0] = f2tf32(pa[j].x); d[1] = f2tf32(pa[j].y);
            d[2] = f2tf32(pa[j].z); d[3] = f2tf32(pa[j].w);
        }
        #pragma unroll
        for (int j = 0; j < 2; j++) {
            int c = (tid & 3) * 8 + j * 4;
            uint32_t* d = &Bs[brow * PAD + c];
            d[0] = f2tf32(pb[j].x); d[1] = f2tf32(pb[j].y);
            d[2] = f2tf32(pb[j].z); d[3] = f2tf32(pb[j].w);
        }
    };

    fetch(0);
    store_buf(0);
    __syncthreads();

    for (int ch = 0; ch < nChunks; ch++) {
        if (ch + 1 < nChunks) fetch((ch + 1) * BK);

        const uint32_t* As = AsBase + (ch & 1) * SMEM_WORDS_A;
        const uint32_t* Bs = BsBase + (ch & 1) * SMEM_WORDS_B;
        #pragma unroll
        for (int kk = 0; kk < 4; kk++) {
            int kb = kk * 8;
            uint32_t af[2][4], bf[4][2];
            #pragma unroll
            for (int m = 0; m < 2; m++) {
                int r = wm * 32 + m * 16 + g;
                af[m][0] = As[r * PAD + kb + tig];
                af[m][1] = As[(r + 8) * PAD + kb + tig];
                af[m][2] = As[r * PAD + kb + tig + 4];
                af[m][3] = As[(r + 8) * PAD + kb + tig + 4];
            }
            #pragma unroll
            for (int n = 0; n < 4; n++) {
                int r = wn * 32 + n * 8 + g;
                bf[n][0] = Bs[r * PAD + kb + tig];
                bf[n][1] = Bs[r * PAD + kb + tig + 4];
            }
            #pragma unroll
            for (int m = 0; m < 2; m++)
                #pragma unroll
                for (int n = 0; n < 4; n++) {
                    asm volatile(
                        "mma.sync.aligned.m16n8k8.row.col.f32.tf32.tf32.f32 "
                        "{%0,%1,%2,%3}, {%4,%5,%6,%7}, {%8,%9}, {%0,%1,%2,%3};\n"
                        : "+f"(acc[m][n][0]), "+f"(acc[m][n][1]),
                          "+f"(acc[m][n][2]), "+f"(acc[m][n][3])
                        : "r"(af[m][0]), "r"(af[m][1]), "r"(af[m][2]), "r"(af[m][3]),
                          "r"(bf[n][0]), "r"(bf[n][1]));
                }
        }

        if (ch + 1 < nChunks) {
            store_buf((ch + 1) & 1);
            __syncthreads();
        }
    }

    // -------- epilogue --------
    #pragma unroll
    for (int m = 0; m < 2; m++) {
        int gr0 = row0 + wm * 32 + m * 16 + g;
        int gr1 = gr0 + 8;
        #pragma unroll
        for (int n = 0; n < 4; n++) {
            int gc = col0 + wn * 32 + n * 8 + 2 * tig;
            float bia0, bia1;
            float *base;
            int cc;
            if (gc < HCV) {
                bia0 = __ldg(&bl[gc]); bia1 = __ldg(&bl[gc + 1]);
                base = Cl; cc = gc;
            } else if (gc < NTOT) {
                cc = gc - HCV;
                bia0 = __ldg(&br[cc]); bia1 = __ldg(&br[cc + 1]);
                base = Cr;
            } else continue;
            if (gr0 < nrows) {
                base[(size_t)gr0 * HCV + cc]     = acc[m][n][0] + bia0;
                base[(size_t)gr0 * HCV + cc + 1] = acc[m][n][1] + bia1;
            }
            if (gr1 < nrows) {
                base[(size_t)gr1 * HCV + cc]     = acc[m][n][2] + bia0;
                base[(size_t)gr1 * HCV + cc + 1] = acc[m][n][3] + bia1;
            }
        }
    }
}

// ---------------- GATv2 node kernel: block per node, warp per head (R12-proven) ------
// Scores are bounded (|s| << 88), so plain exp accumulation is numerically safe;
// the reference's max-subtraction cancels in ex/den exactly.
__global__ __launch_bounds__(128, 12)
void gat_node(const float* __restrict__ att, const float* __restrict__ b) {
    int n    = blockIdx.x;
    int head = threadIdx.x >> 5;
    int lane = threadIdx.x & 31;

    size_t base = (size_t)n * HCV + head * CC;
    const float* atth = att + head * CC;

    float xrr[3], attv[3], out[3];
    #pragma unroll
    for (int j = 0; j < 3; j++) {
        int c = lane + 32 * j;
        bool ok = c < CC;
        xrr[j]  = ok ? g_xr[base + c] : 0.f;
        attv[j] = ok ? __ldg(&atth[c]) : 0.f;
        out[j]  = 0.f;
    }
    int beg = g_off[n], cnt = g_cnt[n];

    float den = 0.f;
    for (int i = 0; i < cnt; i++) {
        const float* xl = g_xl + (size_t)__ldg(&g_csrc[beg + i]) * HCV + head * CC;
        float xv[3];
        float s = 0.f;
        #pragma unroll
        for (int j = 0; j < 3; j++) {
            int c = lane + 32 * j;
            float v = (c < CC) ? xl[c] : 0.f;
            xv[j] = v;
            float f = v + xrr[j];
            f = (f >= 0.f) ? f : 0.2f * f;
            s += f * attv[j];
        }
        #pragma unroll
        for (int o = 16; o; o >>= 1) s += __shfl_xor_sync(0xffffffffu, s, o);

        float e = __expf(s);
        den += e;
        #pragma unroll
        for (int j = 0; j < 3; j++) out[j] += e * xv[j];
    }
    float inv = 1.f / (den + 1e-16f);
    #pragma unroll
    for (int j = 0; j < 3; j++) {
        int c = lane + 32 * j;
        if (c < CC)
            g_h[base + c] = out[j] * inv + __ldg(&b[head * CC + c]);
    }
}

// ---------------- batchnorm ----------------
__global__ void bn_stats(int layer) {
    int t = threadIdx.x;
    if (t >= HCV) return;
    float s = 0.f, sq = 0.f;
    for (int n = blockIdx.x; n < NN; n += gridDim.x) {
        float v = g_h[(size_t)n * HCV + t];
        s += v; sq += v * v;
    }
    atomicAdd(&g_stats[layer][t], s);
    atomicAdd(&g_stats[layer][HCV + t], sq);
}
__global__ void bn_prep(int layer, const float* __restrict__ gamma,
                        const float* __restrict__ beta) {
    int t = threadIdx.x;
    if (t >= HCV) return;
    float mu = g_stats[layer][t] * (1.f / NN);
    float var = g_stats[layer][HCV + t] * (1.f / NN) - mu * mu;
    float sc = rsqrtf(var + BN_EPS) * gamma[t];
    g_bnsc[t] = sc;
    g_bnbt[t] = beta[t] - mu * sc;
}
// flat float4 BN+leaky over g_h: row stride 292 floats = 73 float4
__global__ void bn_apply_v4() {
    int idx = blockIdx.x * blockDim.x + threadIdx.x;
    if (idx >= NN * 73) return;
    int c4 = idx % 73;
    float4 v  = reinterpret_cast<float4*>(g_h)[idx];
    float4 sc = reinterpret_cast<const float4*>(g_bnsc)[c4];
    float4 bt = reinterpret_cast<const float4*>(g_bnbt)[c4];
    float y;
    y = v.x * sc.x + bt.x; v.x = (y >= 0.f) ? y : 0.01f * y;
    y = v.y * sc.y + bt.y; v.y = (y >= 0.f) ? y : 0.01f * y;
    y = v.z * sc.z + bt.z; v.z = (y >= 0.f) ? y : 0.01f * y;
    y = v.w * sc.w + bt.w; v.w = (y >= 0.f) ? y : 0.01f * y;
    reinterpret_cast<float4*>(g_h)[idx] = v;
}

// ---------------- fused layer-2 BN + leaky + classifier ----------------
__global__ void bn_classify(const float* __restrict__ Wc, const float* __restrict__ bc,
                            float* __restrict__ out) {
    int w = (blockIdx.x * blockDim.x + threadIdx.x) >> 5;
    int lane = threadIdx.x & 31;
    if (w >= NN) return;
    const float* hrow = g_h + (size_t)w * HCV;
    float c0 = 0.f, c1 = 0.f;
    #pragma unroll
    for (int k = 0; k < 10; k++) {
        int j = lane + 32 * k;
        if (j < HCV) {
            float y = hrow[j] * __ldg(&g_bnsc[j]) + __ldg(&g_bnbt[j]);
            y = (y >= 0.f) ? y : 0.01f * y;
            c0 += y * __ldg(&Wc[j]);
            c1 += y * __ldg(&Wc[HCV + j]);
        }
    }
    #pragma unroll
    for (int o = 16; o; o >>= 1) {
        c0 += __shfl_xor_sync(0xffffffffu, c0, o);
        c1 += __shfl_xor_sync(0xffffffffu, c1, o);
    }
    if (lane == 0) {
        out[2 * w]     = c0 + bc[0];
        out[2 * w + 1] = c1 + bc[1];
    }
}

// ---------------- host orchestration ----------------
extern "C" void kernel_launch(void* const* d_in, const int* in_sizes, int n_in,
                              void* d_out, int out_size) {
    const float* x    = (const float*)d_in[0];
    const void*  ei   = d_in[1];
    const float* Wl1  = (const float*)d_in[2];
    const float* bl1  = (const float*)d_in[3];
    const float* Wr1  = (const float*)d_in[4];
    const float* br1  = (const float*)d_in[5];
    const float* att1 = (const float*)d_in[6];
    const float* b1   = (const float*)d_in[7];
    const float* Wl2  = (const float*)d_in[8];
    const float* bl2  = (const float*)d_in[9];
    const float* Wr2  = (const float*)d_in[10];
    const float* br2  = (const float*)d_in[11];
    const float* att2 = (const float*)d_in[12];
    const float* b2   = (const float*)d_in[13];
    const float* gamma = (const float*)d_in[14];
    const float* beta  = (const float*)d_in[15];
    const float* Wc   = (const float*)d_in[16];
    const float* bc   = (const float*)d_in[17];
    float* out = (float*)d_out;

    float *xl, *xr, *h;
    cudaGetSymbolAddress((void**)&xl, g_xl);
    cudaGetSymbolAddress((void**)&xr, g_xr);
    cudaGetSymbolAddress((void**)&h,  g_h);

    static int inited = 0;
    static cudaStream_t s2;
    static cudaEvent_t eFork, eJoin;
    if (!inited) {
        cudaFuncSetAttribute(gemm2_tc, cudaFuncAttributeMaxDynamicSharedMemorySize,
                             GEMM_SMEM_BYTES);
        cudaStreamCreateWithFlags(&s2, cudaStreamNonBlocking);
        cudaEventCreateWithFlags(&eFork, cudaEventDisableTiming);
        cudaEventCreateWithFlags(&eJoin, cudaEventDisableTiming);
        inited = 1;
    }

    dim3 ggrid((NN + 127) / 128, (2 * HCV + 63) / 64);     // (391, 10)

    // ---- fork: layer-1 GEMM (depends only on x/weights) runs on s2,
    //      CSR preamble (depends only on edge_index) runs on the capture stream ----
    cudaEventRecord(eFork, 0);
    cudaStreamWaitEvent(s2, eFork, 0);
    gemm2_tc<<<ggrid, 256, GEMM_SMEM_BYTES, s2>>>(x, Wl1, Wr1, bl1, br1, xl, xr, NN, FIN);

    zero_cnt_detect<<<(NN + 255) / 256, 256>>>((const unsigned int*)ei);
    convert_hist<<<(EE + 255) / 256, 256>>>(ei);
    scan_blocksum<<<SCAN_BLKS, 256>>>();
    scan_top<<<1, 256>>>();
    scan_local<<<SCAN_BLKS, 256>>>();
    scatter_csr<<<(EE + 255) / 256, 256>>>(ei);

    cudaEventRecord(eJoin, s2);
    cudaStreamWaitEvent(0, eJoin, 0);

    // ---- layer 1 (joined) ----
    gat_node<<<NN, 128>>>(att1, b1);
    bn_stats<<<512, 320>>>(0);
    bn_prep<<<1, 320>>>(0, gamma, beta);
    bn_apply_v4<<<(NN * 73 + 255) / 256, 256>>>();

    // ---- layer 2 ----
    gemm2_tc<<<ggrid, 256, GEMM_SMEM_BYTES>>>(h, Wl2, Wr2, bl2, br2, xl, xr, NN, HCV);
    gat_node<<<NN, 128>>>(att2, b2);
    bn_stats<<<512, 320>>>(1);
    bn_prep<<<1, 320>>>(1, gamma, beta);
    bn_classify<<<(NN * 32 + 255) / 256, 256>>>(Wc, bc, out);
}